// round 6
// baseline (speedup 1.0000x reference)
#include <cuda_runtime.h>

#define N_ROWS   100000
#define NBINS    512
#define BATCH    8192
#define KNN      16
#define CS_BLKS  128
#define CS_ROWS  (BATCH / CS_BLKS)      // 64 rows per colsum CTA
#define THREADS  512

// Scratch (device allocs forbidden). Fully rewritten every launch.
__device__ float        g_wpart[BATCH];            // w[i] * sum_j add[i][j]
__device__ float        g_bpart[CS_BLKS * NBINS];  // per-strip column sums
__device__ unsigned int g_count = 0;               // ticket; reset by finalizer

// ---------------------------------------------------------------------------
// Kernel A: one CTA per batch row i. 16 warps, warp j owns neighbor j.
// No smem staging: base row read from global per-warp (L1 hit for 15/16 warps),
// so there is NO barrier before the loads — warps run fully independently.
// ---------------------------------------------------------------------------
__global__ __launch_bounds__(THREADS) void pair_kernel(
    const float* __restrict__ outputs,
    const float* __restrict__ y,
    const float* __restrict__ weights,
    float* __restrict__ out_boost)   // -> d_out + 3
{
    __shared__ float s_add[KNN];

    const int i    = blockIdx.x;
    const int tid  = threadIdx.x;
    const int warp = tid >> 5;
    const int lane = tid & 31;

    const int nn = (int)y[i * KNN + warp];
    const float4* nbr4  = reinterpret_cast<const float4*>(outputs + (size_t)nn * NBINS);
    const float4* base4 = reinterpret_cast<const float4*>(outputs + (size_t)i  * NBINS);

    // 8 independent loads per lane: 4 DRAM-ish gathers + 4 L1-shared base loads.
    float4 n0 = nbr4[lane];
    float4 n1 = nbr4[32 + lane];
    float4 n2 = nbr4[64 + lane];
    float4 n3 = nbr4[96 + lane];
    float4 b0 = base4[lane];
    float4 b1 = base4[32 + lane];
    float4 b2 = base4[64 + lane];
    float4 b3 = base4[96 + lane];

    float m0 = fmaxf(fmaxf(b0.x + n0.x, b0.y + n0.y), fmaxf(b0.z + n0.z, b0.w + n0.w));
    float m1 = fmaxf(fmaxf(b1.x + n1.x, b1.y + n1.y), fmaxf(b1.z + n1.z, b1.w + n1.w));
    float m2 = fmaxf(fmaxf(b2.x + n2.x, b2.y + n2.y), fmaxf(b2.z + n2.z, b2.w + n2.w));
    float m3 = fmaxf(fmaxf(b3.x + n3.x, b3.y + n3.y), fmaxf(b3.z + n3.z, b3.w + n3.w));
    float m  = fmaxf(fmaxf(m0, m1), fmaxf(m2, m3));

#pragma unroll
    for (int o = 16; o; o >>= 1)
        m = fmaxf(m, __shfl_xor_sync(0xffffffffu, m, o));
    if (lane == 0) s_add[warp] = m;
    __syncthreads();

    if (tid == 0) {
        float s = 0.f;
#pragma unroll
        for (int j = 0; j < KNN; j++) s += s_add[j];
        out_boost[i] = fmaxf((2.0f - s * (1.0f / KNN)) * 0.5f, 0.5f);  // booster
        g_wpart[i]   = s * weights[i];
    }
}

// ---------------------------------------------------------------------------
// Kernel B: column-sum strips + in-kernel finalizer via 128-CTA ticket.
// g_wpart is produced by kernel A (prior launch -> globally visible).
// ---------------------------------------------------------------------------
__global__ __launch_bounds__(THREADS) void epilogue_kernel(
    const float* __restrict__ outputs,
    float* __restrict__ d_out)
{
    __shared__ unsigned s_ticket;
    __shared__ float    s_max[THREADS];
    __shared__ float    s_min[THREADS];
    __shared__ double   s_sum[THREADS];

    const int bid = blockIdx.x;
    const int tid = threadIdx.x;

    // Strip sum: thread t owns bin t over CS_ROWS rows (coalesced).
    {
        const float* p = outputs + (size_t)bid * CS_ROWS * NBINS + tid;
        float s = 0.f;
#pragma unroll 8
        for (int r = 0; r < CS_ROWS; r++) s += p[(size_t)r * NBINS];
        g_bpart[bid * NBINS + tid] = s;
    }

    // Release ticket (128 atomics total — negligible).
    if (tid == 0) {
        unsigned t;
        asm volatile("atom.add.release.gpu.global.u32 %0, [%1], 1;"
                     : "=r"(t) : "l"(&g_count) : "memory");
        s_ticket = t;
    }
    __syncthreads();

    if (s_ticket == CS_BLKS - 1) {
        asm volatile("fence.acq_rel.gpu;" ::: "memory");   // acquire side

        // Column totals: thread t owns bin t.
        float col = 0.f;
#pragma unroll 8
        for (int b = 0; b < CS_BLKS; b++) col += __ldcg(&g_bpart[b * NBINS + tid]);

        // Weighted-sum (double accumulation, fixed order).
        double ws = 0.0;
#pragma unroll 4
        for (int r = tid; r < BATCH; r += THREADS) ws += (double)g_wpart[r];

        s_max[tid] = col; s_min[tid] = col; s_sum[tid] = ws;
        __syncthreads();
        for (int o = THREADS / 2; o; o >>= 1) {
            if (tid < o) {
                s_max[tid] = fmaxf(s_max[tid], s_max[tid + o]);
                s_min[tid] = fminf(s_min[tid], s_min[tid + o]);
                s_sum[tid] += s_sum[tid + o];
            }
            __syncthreads();
        }

        if (tid == 0) {
            float bspread  = s_max[0] - s_min[0];
            float ratio    = bspread / ((float)N_ROWS / (float)NBINS);
            float add_mean = (float)(s_sum[0] / (double)(BATCH * KNN));
            float d        = 2.0f - add_mean;
            d = d * d;
            d_out[0] = ratio + d;   // cost
            d_out[1] = d;           // diff
            d_out[2] = ratio;       // b / target_b
            g_count  = 0;           // reset for next graph replay
        }
    }
}

// ---------------------------------------------------------------------------
extern "C" void kernel_launch(void* const* d_in, const int* in_sizes, int n_in,
                              void* d_out, int out_size)
{
    const float* outputs = (const float*)d_in[0];  // (100000, 512) f32
    const float* y       = (const float*)d_in[1];  // (8192, 16)   f32 indices
    const float* weights = (const float*)d_in[2];  // (8192,)      f32
    float* out = (float*)d_out;                    // [cost, diff, ratio, boost(8192)]

    pair_kernel<<<BATCH, THREADS>>>(outputs, y, weights, out + 3);
    epilogue_kernel<<<CS_BLKS, THREADS>>>(outputs, out);
}

// round 7
// speedup vs baseline: 1.0734x; 1.0734x over previous
#include <cuda_runtime.h>

#define N_ROWS   100000
#define NBINS    512
#define BATCH    8192
#define KNN      16
#define CS_BLKS  256
#define CS_ROWS  (BATCH / CS_BLKS)      // 32 rows per colsum CTA
#define THREADS  512

// Scratch (device allocs forbidden). Fully rewritten every launch.
__device__ float        g_wpart[BATCH];            // w[i] * sum_j add[i][j]
__device__ float        g_bpart[CS_BLKS * NBINS];  // per-strip column sums
__device__ unsigned int g_count = 0;               // ticket; reset by finalizer

// ---------------------------------------------------------------------------
// Kernel A: one CTA per batch row i. 16 warps, warp j owns neighbor j.
// Barrier-free until the 16-value reduce; base row served from L1.
// ---------------------------------------------------------------------------
__global__ __launch_bounds__(THREADS) void pair_kernel(
    const float* __restrict__ outputs,
    const float* __restrict__ y,
    const float* __restrict__ weights,
    float* __restrict__ out_boost)   // -> d_out + 3
{
    __shared__ float s_add[KNN];

    // Let the PDL-dependent epilogue launch immediately (it only needs our
    // results inside its finalizer, which grid-syncs explicitly).
    cudaTriggerProgrammaticLaunchCompletion();

    const int i    = blockIdx.x;
    const int tid  = threadIdx.x;
    const int warp = tid >> 5;
    const int lane = tid & 31;

    const int nn = (int)y[i * KNN + warp];
    const float4* nbr4  = reinterpret_cast<const float4*>(outputs + (size_t)nn * NBINS);
    const float4* base4 = reinterpret_cast<const float4*>(outputs + (size_t)i  * NBINS);

    // 8 independent loads per lane: 4 gathers + 4 L1-shared base loads.
    float4 n0 = nbr4[lane];
    float4 n1 = nbr4[32 + lane];
    float4 n2 = nbr4[64 + lane];
    float4 n3 = nbr4[96 + lane];
    float4 b0 = base4[lane];
    float4 b1 = base4[32 + lane];
    float4 b2 = base4[64 + lane];
    float4 b3 = base4[96 + lane];

    float m0 = fmaxf(fmaxf(b0.x + n0.x, b0.y + n0.y), fmaxf(b0.z + n0.z, b0.w + n0.w));
    float m1 = fmaxf(fmaxf(b1.x + n1.x, b1.y + n1.y), fmaxf(b1.z + n1.z, b1.w + n1.w));
    float m2 = fmaxf(fmaxf(b2.x + n2.x, b2.y + n2.y), fmaxf(b2.z + n2.z, b2.w + n2.w));
    float m3 = fmaxf(fmaxf(b3.x + n3.x, b3.y + n3.y), fmaxf(b3.z + n3.z, b3.w + n3.w));
    float m  = fmaxf(fmaxf(m0, m1), fmaxf(m2, m3));

#pragma unroll
    for (int o = 16; o; o >>= 1)
        m = fmaxf(m, __shfl_xor_sync(0xffffffffu, m, o));
    if (lane == 0) s_add[warp] = m;
    __syncthreads();

    if (tid == 0) {
        float s = 0.f;
#pragma unroll
        for (int j = 0; j < KNN; j++) s += s_add[j];
        out_boost[i] = fmaxf((2.0f - s * (1.0f / KNN)) * 0.5f, 0.5f);  // booster
        g_wpart[i]   = s * weights[i];
    }
}

// ---------------------------------------------------------------------------
// Kernel B (PDL secondary): column-sum strips run CONCURRENTLY with kernel A
// (they read only `outputs`). The single finalizer CTA grid-syncs on kernel A
// before consuming g_wpart.
// ---------------------------------------------------------------------------
__global__ __launch_bounds__(THREADS) void epilogue_kernel(
    const float* __restrict__ outputs,
    float* __restrict__ d_out)
{
    __shared__ unsigned s_ticket;
    __shared__ float    s_max[THREADS];
    __shared__ float    s_min[THREADS];
    __shared__ double   s_sum[THREADS];

    const int bid = blockIdx.x;
    const int tid = threadIdx.x;

    // Strip sum: thread t owns bin t over CS_ROWS rows; explicit temp batch
    // of 16 keeps 16 LDGs in flight.
    {
        const float* p = outputs + (size_t)bid * CS_ROWS * NBINS + tid;
        float s = 0.f;
#pragma unroll
        for (int rb = 0; rb < CS_ROWS; rb += 16) {
            float t16[16];
#pragma unroll
            for (int r = 0; r < 16; r++) t16[r] = p[(size_t)(rb + r) * NBINS];
#pragma unroll
            for (int r = 0; r < 16; r++) s += t16[r];
        }
        g_bpart[bid * NBINS + tid] = s;
    }

    // Release ticket (256 atomics total — negligible).
    if (tid == 0) {
        unsigned t;
        asm volatile("atom.add.release.gpu.global.u32 %0, [%1], 1;"
                     : "=r"(t) : "l"(&g_count) : "memory");
        s_ticket = t;
    }
    __syncthreads();

    if (s_ticket == CS_BLKS - 1) {
        // Wait for pair_kernel's g_wpart to be complete & visible.
        cudaGridDependencySynchronize();
        asm volatile("fence.acq_rel.gpu;" ::: "memory");   // strips acquire

        // Column totals: thread t owns bin t; batch 16 L2 loads.
        float col = 0.f;
#pragma unroll
        for (int bb = 0; bb < CS_BLKS; bb += 16) {
            float t16[16];
#pragma unroll
            for (int b = 0; b < 16; b++) t16[b] = __ldcg(&g_bpart[(bb + b) * NBINS + tid]);
#pragma unroll
            for (int b = 0; b < 16; b++) col += t16[b];
        }

        // Weighted-sum (double accumulation, fixed order).
        double ws = 0.0;
#pragma unroll
        for (int r = tid; r < BATCH; r += THREADS) ws += (double)g_wpart[r];

        s_max[tid] = col; s_min[tid] = col; s_sum[tid] = ws;
        __syncthreads();
        for (int o = THREADS / 2; o; o >>= 1) {
            if (tid < o) {
                s_max[tid] = fmaxf(s_max[tid], s_max[tid + o]);
                s_min[tid] = fminf(s_min[tid], s_min[tid + o]);
                s_sum[tid] += s_sum[tid + o];
            }
            __syncthreads();
        }

        if (tid == 0) {
            float bspread  = s_max[0] - s_min[0];
            float ratio    = bspread / ((float)N_ROWS / (float)NBINS);
            float add_mean = (float)(s_sum[0] / (double)(BATCH * KNN));
            float d        = 2.0f - add_mean;
            d = d * d;
            d_out[0] = ratio + d;   // cost
            d_out[1] = d;           // diff
            d_out[2] = ratio;       // b / target_b
            g_count  = 0;           // reset for next graph replay
        }
    }
}

// ---------------------------------------------------------------------------
extern "C" void kernel_launch(void* const* d_in, const int* in_sizes, int n_in,
                              void* d_out, int out_size)
{
    const float* outputs = (const float*)d_in[0];  // (100000, 512) f32
    const float* y       = (const float*)d_in[1];  // (8192, 16)   f32 indices
    const float* weights = (const float*)d_in[2];  // (8192,)      f32
    float* out = (float*)d_out;                    // [cost, diff, ratio, boost(8192)]

    pair_kernel<<<BATCH, THREADS>>>(outputs, y, weights, out + 3);

    // PDL: epilogue launches while pair_kernel is still running; its strip
    // phase is independent, and its finalizer grid-syncs before reading
    // pair results.
    cudaLaunchConfig_t cfg = {};
    cfg.gridDim  = dim3(CS_BLKS, 1, 1);
    cfg.blockDim = dim3(THREADS, 1, 1);
    cudaLaunchAttribute attr[1];
    attr[0].id = cudaLaunchAttributeProgrammaticStreamSerialization;
    attr[0].val.programmaticStreamSerializationAllowed = 1;
    cfg.attrs    = attr;
    cfg.numAttrs = 1;
    cudaLaunchKernelEx(&cfg, epilogue_kernel, outputs, out);
}

// round 8
// speedup vs baseline: 1.1534x; 1.0746x over previous
#include <cuda_runtime.h>

#define N_ROWS   100000
#define NBINS    512
#define BATCH    8192
#define KNN      16
#define COL_BLKS 64
#define CS_ROWS  (BATCH / COL_BLKS)     // 128 rows per colsum CTA
#define THREADS  512
#define TOTAL_BLKS (BATCH + COL_BLKS)

// Scratch (device allocs forbidden). Fully rewritten every launch.
__device__ float g_wpart[BATCH];             // w[i] * sum_j add[i][j]
__device__ float g_bpart[COL_BLKS * NBINS];  // per-strip column sums

// ---------------------------------------------------------------------------
// Kernel A: fused grid. bid<64: column-sum strip. bid>=64: pair row i.
// NO cross-CTA sync of any kind — the launch boundary orders everything.
// ---------------------------------------------------------------------------
__global__ __launch_bounds__(THREADS) void main_kernel(
    const float* __restrict__ outputs,
    const float* __restrict__ y,
    const float* __restrict__ weights,
    float* __restrict__ out_boost)   // -> d_out + 3
{
    __shared__ float s_add[KNN];

    const int bid = blockIdx.x;
    const int tid = threadIdx.x;

    if (bid < COL_BLKS) {
        // ---- Column-sum strip: thread t owns bin t over 128 rows (coalesced).
        const float* p = outputs + (size_t)bid * CS_ROWS * NBINS + tid;
        float s = 0.f;
#pragma unroll
        for (int rb = 0; rb < CS_ROWS; rb += 8) {
            float t8[8];
#pragma unroll
            for (int r = 0; r < 8; r++) t8[r] = p[(size_t)(rb + r) * NBINS];
#pragma unroll
            for (int r = 0; r < 8; r++) s += t8[r];
        }
        g_bpart[bid * NBINS + tid] = s;
        return;
    }

    // ---- Pair work for batch row i: 16 warps, warp j owns neighbor j.
    const int i    = bid - COL_BLKS;
    const int warp = tid >> 5;
    const int lane = tid & 31;

    const int nn = (int)y[i * KNN + warp];
    const float4* nbr4  = reinterpret_cast<const float4*>(outputs + (size_t)nn * NBINS);
    const float4* base4 = reinterpret_cast<const float4*>(outputs + (size_t)i  * NBINS);

    // 8 independent loads per lane: 4 gathers (DRAM/L2) + 4 base (L1-shared).
    float4 n0 = nbr4[lane];
    float4 n1 = nbr4[32 + lane];
    float4 n2 = nbr4[64 + lane];
    float4 n3 = nbr4[96 + lane];
    float4 b0 = base4[lane];
    float4 b1 = base4[32 + lane];
    float4 b2 = base4[64 + lane];
    float4 b3 = base4[96 + lane];

    float m0 = fmaxf(fmaxf(b0.x + n0.x, b0.y + n0.y), fmaxf(b0.z + n0.z, b0.w + n0.w));
    float m1 = fmaxf(fmaxf(b1.x + n1.x, b1.y + n1.y), fmaxf(b1.z + n1.z, b1.w + n1.w));
    float m2 = fmaxf(fmaxf(b2.x + n2.x, b2.y + n2.y), fmaxf(b2.z + n2.z, b2.w + n2.w));
    float m3 = fmaxf(fmaxf(b3.x + n3.x, b3.y + n3.y), fmaxf(b3.z + n3.z, b3.w + n3.w));
    float m  = fmaxf(fmaxf(m0, m1), fmaxf(m2, m3));

#pragma unroll
    for (int o = 16; o; o >>= 1)
        m = fmaxf(m, __shfl_xor_sync(0xffffffffu, m, o));
    if (lane == 0) s_add[warp] = m;
    __syncthreads();

    if (tid == 0) {
        float s = 0.f;
#pragma unroll
        for (int j = 0; j < KNN; j++) s += s_add[j];
        out_boost[i] = fmaxf((2.0f - s * (1.0f / KNN)) * 0.5f, 0.5f);  // booster
        g_wpart[i]   = s * weights[i];
    }
}

// ---------------------------------------------------------------------------
// Kernel B: single-CTA finalizer (~160 KB of scratch reads).
// ---------------------------------------------------------------------------
__global__ __launch_bounds__(THREADS) void final_kernel(float* __restrict__ d_out)
{
    __shared__ float  s_max[THREADS];
    __shared__ float  s_min[THREADS];
    __shared__ double s_sum[THREADS];

    const int tid = threadIdx.x;

    // Column totals: thread t owns bin t; batch 8 loads for MLP.
    float col = 0.f;
#pragma unroll
    for (int bb = 0; bb < COL_BLKS; bb += 8) {
        float t8[8];
#pragma unroll
        for (int b = 0; b < 8; b++) t8[b] = g_bpart[(bb + b) * NBINS + tid];
#pragma unroll
        for (int b = 0; b < 8; b++) col += t8[b];
    }

    // Weighted-sum reduction (double accumulation, fixed order).
    double ws = 0.0;
#pragma unroll
    for (int r = tid; r < BATCH; r += THREADS) ws += (double)g_wpart[r];

    s_max[tid] = col; s_min[tid] = col; s_sum[tid] = ws;
    __syncthreads();
    for (int o = THREADS / 2; o; o >>= 1) {
        if (tid < o) {
            s_max[tid] = fmaxf(s_max[tid], s_max[tid + o]);
            s_min[tid] = fminf(s_min[tid], s_min[tid + o]);
            s_sum[tid] += s_sum[tid + o];
        }
        __syncthreads();
    }

    if (tid == 0) {
        float bspread  = s_max[0] - s_min[0];
        float ratio    = bspread / ((float)N_ROWS / (float)NBINS);
        float add_mean = (float)(s_sum[0] / (double)(BATCH * KNN));
        float d        = 2.0f - add_mean;
        d = d * d;
        d_out[0] = ratio + d;   // cost
        d_out[1] = d;           // diff
        d_out[2] = ratio;       // b / target_b
    }
}

// ---------------------------------------------------------------------------
extern "C" void kernel_launch(void* const* d_in, const int* in_sizes, int n_in,
                              void* d_out, int out_size)
{
    const float* outputs = (const float*)d_in[0];  // (100000, 512) f32
    const float* y       = (const float*)d_in[1];  // (8192, 16)   f32 indices
    const float* weights = (const float*)d_in[2];  // (8192,)      f32
    float* out = (float*)d_out;                    // [cost, diff, ratio, boost(8192)]

    main_kernel<<<TOTAL_BLKS, THREADS>>>(outputs, y, weights, out + 3);
    final_kernel<<<1, THREADS>>>(out);
}

// round 9
// speedup vs baseline: 1.2062x; 1.0457x over previous
#include <cuda_runtime.h>

#define N_ROWS   100000
#define NBINS    512
#define BATCH    8192
#define KNN      16
#define COL_BLKS 64
#define CS_ROWS  (BATCH / COL_BLKS)     // 128 rows per colsum CTA
#define THREADS  512
#define FTHREADS 1024
#define TOTAL_BLKS (BATCH + COL_BLKS)

// Scratch (device allocs forbidden). Fully rewritten every launch.
__device__ float g_wpart[BATCH];             // w[i] * sum_j add[i][j]
__device__ float g_bpart[COL_BLKS * NBINS];  // per-strip column sums

// ---------------------------------------------------------------------------
// Kernel A: fused grid. bid<64: column-sum strip. bid>=64: pair row i.
// NO cross-CTA sync — the launch boundary orders everything. (Proven 39 us.)
// ---------------------------------------------------------------------------
__global__ __launch_bounds__(THREADS) void main_kernel(
    const float* __restrict__ outputs,
    const float* __restrict__ y,
    const float* __restrict__ weights,
    float* __restrict__ out_boost)   // -> d_out + 3
{
    __shared__ float s_add[KNN];

    const int bid = blockIdx.x;
    const int tid = threadIdx.x;

    if (bid < COL_BLKS) {
        // Column-sum strip: thread t owns bin t over 128 rows (coalesced).
        const float* p = outputs + (size_t)bid * CS_ROWS * NBINS + tid;
        float s = 0.f;
#pragma unroll
        for (int rb = 0; rb < CS_ROWS; rb += 8) {
            float t8[8];
#pragma unroll
            for (int r = 0; r < 8; r++) t8[r] = p[(size_t)(rb + r) * NBINS];
#pragma unroll
            for (int r = 0; r < 8; r++) s += t8[r];
        }
        g_bpart[bid * NBINS + tid] = s;
        return;
    }

    // Pair work for batch row i: 16 warps, warp j owns neighbor j.
    const int i    = bid - COL_BLKS;
    const int warp = tid >> 5;
    const int lane = tid & 31;

    const int nn = (int)y[i * KNN + warp];
    const float4* nbr4  = reinterpret_cast<const float4*>(outputs + (size_t)nn * NBINS);
    const float4* base4 = reinterpret_cast<const float4*>(outputs + (size_t)i  * NBINS);

    float4 n0 = nbr4[lane];
    float4 n1 = nbr4[32 + lane];
    float4 n2 = nbr4[64 + lane];
    float4 n3 = nbr4[96 + lane];
    float4 b0 = base4[lane];
    float4 b1 = base4[32 + lane];
    float4 b2 = base4[64 + lane];
    float4 b3 = base4[96 + lane];

    float m0 = fmaxf(fmaxf(b0.x + n0.x, b0.y + n0.y), fmaxf(b0.z + n0.z, b0.w + n0.w));
    float m1 = fmaxf(fmaxf(b1.x + n1.x, b1.y + n1.y), fmaxf(b1.z + n1.z, b1.w + n1.w));
    float m2 = fmaxf(fmaxf(b2.x + n2.x, b2.y + n2.y), fmaxf(b2.z + n2.z, b2.w + n2.w));
    float m3 = fmaxf(fmaxf(b3.x + n3.x, b3.y + n3.y), fmaxf(b3.z + n3.z, b3.w + n3.w));
    float m  = fmaxf(fmaxf(m0, m1), fmaxf(m2, m3));

#pragma unroll
    for (int o = 16; o; o >>= 1)
        m = fmaxf(m, __shfl_xor_sync(0xffffffffu, m, o));
    if (lane == 0) s_add[warp] = m;
    __syncthreads();

    if (tid == 0) {
        float s = 0.f;
#pragma unroll
        for (int j = 0; j < KNN; j++) s += s_add[j];
        out_boost[i] = fmaxf((2.0f - s * (1.0f / KNN)) * 0.5f, 0.5f);  // booster
        g_wpart[i]   = s * weights[i];
    }
}

// ---------------------------------------------------------------------------
// Kernel B: 1-CTA finalizer, 1024 threads, work split by warp half:
//   warps 0-15 : column totals (bin t) -> max/min
//   warps 16-31: weighted sum over g_wpart (4 independent fp64 chains)
// Warp shuffles + ONE barrier instead of a 9-round smem tree.
// Launched with PDL; grid-dep-sync below orders it after main_kernel.
// ---------------------------------------------------------------------------
__global__ __launch_bounds__(FTHREADS) void final_kernel(float* __restrict__ d_out)
{
    cudaGridDependencySynchronize();   // wait for main_kernel completion

    __shared__ float  s_wmax[16];
    __shared__ float  s_wmin[16];
    __shared__ double s_wsum[16];

    const int tid  = threadIdx.x;
    const int warp = tid >> 5;
    const int lane = tid & 31;

    if (warp < 16) {
        // ---- Column totals: thread t (0..511) owns bin t; coalesced loads.
        float col = 0.f;
#pragma unroll
        for (int bb = 0; bb < COL_BLKS; bb += 16) {
            float t16[16];
#pragma unroll
            for (int b = 0; b < 16; b++) t16[b] = g_bpart[(bb + b) * NBINS + tid];
#pragma unroll
            for (int b = 0; b < 16; b++) col += t16[b];
        }
        float mx = col, mn = col;
#pragma unroll
        for (int o = 16; o; o >>= 1) {
            mx = fmaxf(mx, __shfl_xor_sync(0xffffffffu, mx, o));
            mn = fminf(mn, __shfl_xor_sync(0xffffffffu, mn, o));
        }
        if (lane == 0) { s_wmax[warp] = mx; s_wmin[warp] = mn; }
    } else {
        // ---- Weighted sum: thread r0 = tid-512 (0..511), stride 512, 16 iters,
        // coalesced; 4 independent fp64 accumulators to break the add chain.
        const int r0 = tid - 512;
        double a0 = 0.0, a1 = 0.0, a2 = 0.0, a3 = 0.0;
#pragma unroll
        for (int it = 0; it < 4; it++) {
            a0 += (double)g_wpart[r0 + (it * 4 + 0) * 512];
            a1 += (double)g_wpart[r0 + (it * 4 + 1) * 512];
            a2 += (double)g_wpart[r0 + (it * 4 + 2) * 512];
            a3 += (double)g_wpart[r0 + (it * 4 + 3) * 512];
        }
        double ws = (a0 + a1) + (a2 + a3);
#pragma unroll
        for (int o = 16; o; o >>= 1)
            ws += __shfl_xor_sync(0xffffffffu, ws, o);
        if (lane == 0) s_wsum[warp - 16] = ws;
    }
    __syncthreads();

    if (warp == 0) {
        float  mx = (lane < 16) ? s_wmax[lane] : -1e30f;
        float  mn = (lane < 16) ? s_wmin[lane] :  1e30f;
        double ws = (lane < 16) ? s_wsum[lane] :  0.0;
#pragma unroll
        for (int o = 8; o; o >>= 1) {
            mx = fmaxf(mx, __shfl_xor_sync(0xffffffffu, mx, o));
            mn = fminf(mn, __shfl_xor_sync(0xffffffffu, mn, o));
            ws += __shfl_xor_sync(0xffffffffu, ws, o);
        }
        if (lane == 0) {
            float bspread  = mx - mn;
            float ratio    = bspread / ((float)N_ROWS / (float)NBINS);
            float add_mean = (float)(ws / (double)(BATCH * KNN));
            float d        = 2.0f - add_mean;
            d = d * d;
            d_out[0] = ratio + d;   // cost
            d_out[1] = d;           // diff
            d_out[2] = ratio;       // b / target_b
        }
    }
}

// ---------------------------------------------------------------------------
extern "C" void kernel_launch(void* const* d_in, const int* in_sizes, int n_in,
                              void* d_out, int out_size)
{
    const float* outputs = (const float*)d_in[0];  // (100000, 512) f32
    const float* y       = (const float*)d_in[1];  // (8192, 16)   f32 indices
    const float* weights = (const float*)d_in[2];  // (8192,)      f32
    float* out = (float*)d_out;                    // [cost, diff, ratio, boost(8192)]

    main_kernel<<<TOTAL_BLKS, THREADS>>>(outputs, y, weights, out + 3);

    // PDL: finalizer's launch/setup overlaps main_kernel's drain; the
    // grid-dep-sync inside orders its reads after main completes.
    cudaLaunchConfig_t cfg = {};
    cfg.gridDim  = dim3(1, 1, 1);
    cfg.blockDim = dim3(FTHREADS, 1, 1);
    cudaLaunchAttribute attr[1];
    attr[0].id = cudaLaunchAttributeProgrammaticStreamSerialization;
    attr[0].val.programmaticStreamSerializationAllowed = 1;
    cfg.attrs    = attr;
    cfg.numAttrs = 1;
    cudaLaunchKernelEx(&cfg, final_kernel, out);
}

// round 10
// speedup vs baseline: 1.2070x; 1.0006x over previous
#include <cuda_runtime.h>

#define N_ROWS   100000
#define NBINS    512
#define BATCH    8192
#define KNN      16
#define COL_BLKS 64
#define CS_ROWS  (BATCH / COL_BLKS)     // 128 rows per colsum CTA
#define THREADS  512
#define FTHREADS 1024
#define TOTAL_BLKS (BATCH + COL_BLKS)

// Scratch (device allocs forbidden). Fully rewritten every launch.
__device__ float g_wpart[BATCH];             // w[i] * sum_j add[i][j]
__device__ float g_bpart[COL_BLKS * NBINS];  // per-strip column sums

// ---------------------------------------------------------------------------
// Kernel A: fused grid. bid<64: column-sum strip. bid>=64: pair row i.
// No cross-CTA sync — the launch boundary orders everything.
// ---------------------------------------------------------------------------
__global__ __launch_bounds__(THREADS) void main_kernel(
    const float* __restrict__ outputs,
    const float* __restrict__ y,
    const float* __restrict__ weights,
    float* __restrict__ out_boost)   // -> d_out + 3
{
    __shared__ float s_add[KNN];

    // PDL: release the dependent finalizer launch early. It sleeps in
    // cudaGridDependencySynchronize() until this grid completes, so this
    // costs us nothing and hides the finalizer's launch latency.
    cudaTriggerProgrammaticLaunchCompletion();

    const int bid = blockIdx.x;
    const int tid = threadIdx.x;

    if (bid < COL_BLKS) {
        // Column-sum strip: thread t owns bin t over 128 rows (coalesced).
        const float* p = outputs + (size_t)bid * CS_ROWS * NBINS + tid;
        float s = 0.f;
#pragma unroll
        for (int rb = 0; rb < CS_ROWS; rb += 8) {
            float t8[8];
#pragma unroll
            for (int r = 0; r < 8; r++) t8[r] = p[(size_t)(rb + r) * NBINS];
#pragma unroll
            for (int r = 0; r < 8; r++) s += t8[r];
        }
        g_bpart[bid * NBINS + tid] = s;
        return;
    }

    // Pair work for batch row i: 16 warps, warp j owns neighbor j.
    const int i    = bid - COL_BLKS;
    const int warp = tid >> 5;
    const int lane = tid & 31;

    const int nn = (int)y[i * KNN + warp];
    const float4* nbr4  = reinterpret_cast<const float4*>(outputs + (size_t)nn * NBINS);
    const float4* base4 = reinterpret_cast<const float4*>(outputs + (size_t)i  * NBINS);

    // 8 independent loads per lane: 4 gathers (DRAM/L2) + 4 base (L1-shared).
    float4 n0 = nbr4[lane];
    float4 n1 = nbr4[32 + lane];
    float4 n2 = nbr4[64 + lane];
    float4 n3 = nbr4[96 + lane];
    float4 b0 = base4[lane];
    float4 b1 = base4[32 + lane];
    float4 b2 = base4[64 + lane];
    float4 b3 = base4[96 + lane];

    float m0 = fmaxf(fmaxf(b0.x + n0.x, b0.y + n0.y), fmaxf(b0.z + n0.z, b0.w + n0.w));
    float m1 = fmaxf(fmaxf(b1.x + n1.x, b1.y + n1.y), fmaxf(b1.z + n1.z, b1.w + n1.w));
    float m2 = fmaxf(fmaxf(b2.x + n2.x, b2.y + n2.y), fmaxf(b2.z + n2.z, b2.w + n2.w));
    float m3 = fmaxf(fmaxf(b3.x + n3.x, b3.y + n3.y), fmaxf(b3.z + n3.z, b3.w + n3.w));
    float m  = fmaxf(fmaxf(m0, m1), fmaxf(m2, m3));

#pragma unroll
    for (int o = 16; o; o >>= 1)
        m = fmaxf(m, __shfl_xor_sync(0xffffffffu, m, o));
    if (lane == 0) s_add[warp] = m;
    __syncthreads();

    if (tid == 0) {
        float s = 0.f;
#pragma unroll
        for (int j = 0; j < KNN; j++) s += s_add[j];
        out_boost[i] = fmaxf((2.0f - s * (1.0f / KNN)) * 0.5f, 0.5f);  // booster
        g_wpart[i]   = s * weights[i];
    }
}

// ---------------------------------------------------------------------------
// Kernel B: 1-CTA finalizer, 1024 threads.
//   warps 0-15 : column totals (bin t) -> max/min
//   warps 16-31: weighted sum over g_wpart (4 independent fp64 chains)
// PDL secondary: pre-launched, sleeps until main_kernel completes.
// ---------------------------------------------------------------------------
__global__ __launch_bounds__(FTHREADS) void final_kernel(float* __restrict__ d_out)
{
    cudaGridDependencySynchronize();   // wait for main_kernel completion

    __shared__ float  s_wmax[16];
    __shared__ float  s_wmin[16];
    __shared__ double s_wsum[16];

    const int tid  = threadIdx.x;
    const int warp = tid >> 5;
    const int lane = tid & 31;

    if (warp < 16) {
        // Column totals: thread t (0..511) owns bin t; coalesced loads.
        float col = 0.f;
#pragma unroll
        for (int bb = 0; bb < COL_BLKS; bb += 16) {
            float t16[16];
#pragma unroll
            for (int b = 0; b < 16; b++) t16[b] = g_bpart[(bb + b) * NBINS + tid];
#pragma unroll
            for (int b = 0; b < 16; b++) col += t16[b];
        }
        float mx = col, mn = col;
#pragma unroll
        for (int o = 16; o; o >>= 1) {
            mx = fmaxf(mx, __shfl_xor_sync(0xffffffffu, mx, o));
            mn = fminf(mn, __shfl_xor_sync(0xffffffffu, mn, o));
        }
        if (lane == 0) { s_wmax[warp] = mx; s_wmin[warp] = mn; }
    } else {
        // Weighted sum: thread r0 = tid-512, stride 512, 16 iters, coalesced;
        // 4 independent fp64 accumulators break the DFMA latency chain.
        const int r0 = tid - 512;
        double a0 = 0.0, a1 = 0.0, a2 = 0.0, a3 = 0.0;
#pragma unroll
        for (int it = 0; it < 4; it++) {
            a0 += (double)g_wpart[r0 + (it * 4 + 0) * 512];
            a1 += (double)g_wpart[r0 + (it * 4 + 1) * 512];
            a2 += (double)g_wpart[r0 + (it * 4 + 2) * 512];
            a3 += (double)g_wpart[r0 + (it * 4 + 3) * 512];
        }
        double ws = (a0 + a1) + (a2 + a3);
#pragma unroll
        for (int o = 16; o; o >>= 1)
            ws += __shfl_xor_sync(0xffffffffu, ws, o);
        if (lane == 0) s_wsum[warp - 16] = ws;
    }
    __syncthreads();

    if (warp == 0) {
        float  mx = (lane < 16) ? s_wmax[lane] : -1e30f;
        float  mn = (lane < 16) ? s_wmin[lane] :  1e30f;
        double ws = (lane < 16) ? s_wsum[lane] :  0.0;
#pragma unroll
        for (int o = 8; o; o >>= 1) {
            mx = fmaxf(mx, __shfl_xor_sync(0xffffffffu, mx, o));
            mn = fminf(mn, __shfl_xor_sync(0xffffffffu, mn, o));
            ws += __shfl_xor_sync(0xffffffffu, ws, o);
        }
        if (lane == 0) {
            float bspread  = mx - mn;
            float ratio    = bspread / ((float)N_ROWS / (float)NBINS);
            float add_mean = (float)(ws / (double)(BATCH * KNN));
            float d        = 2.0f - add_mean;
            d = d * d;
            d_out[0] = ratio + d;   // cost
            d_out[1] = d;           // diff
            d_out[2] = ratio;       // b / target_b
        }
    }
}

// ---------------------------------------------------------------------------
extern "C" void kernel_launch(void* const* d_in, const int* in_sizes, int n_in,
                              void* d_out, int out_size)
{
    const float* outputs = (const float*)d_in[0];  // (100000, 512) f32
    const float* y       = (const float*)d_in[1];  // (8192, 16)   f32 indices
    const float* weights = (const float*)d_in[2];  // (8192,)      f32
    float* out = (float*)d_out;                    // [cost, diff, ratio, boost(8192)]

    main_kernel<<<TOTAL_BLKS, THREADS>>>(outputs, y, weights, out + 3);

    // PDL: finalizer pre-launches while main_kernel runs; its grid-dep-sync
    // orders its reads after main completes.
    cudaLaunchConfig_t cfg = {};
    cfg.gridDim  = dim3(1, 1, 1);
    cfg.blockDim = dim3(FTHREADS, 1, 1);
    cudaLaunchAttribute attr[1];
    attr[0].id = cudaLaunchAttributeProgrammaticStreamSerialization;
    attr[0].val.programmaticStreamSerializationAllowed = 1;
    cfg.attrs    = attr;
    cfg.numAttrs = 1;
    cudaLaunchKernelEx(&cfg, final_kernel, out);
}

// round 11
// speedup vs baseline: 1.2164x; 1.0078x over previous
#include <cuda_runtime.h>

#define N_ROWS   100000
#define NBINS    512
#define BATCH    8192
#define KNN      16
#define COL_BLKS 64
#define CS_ROWS  (BATCH / COL_BLKS)     // 128 rows per colsum CTA
#define THREADS  512
#define F_BLKS   8
#define STRIPS_PER_FCTA (COL_BLKS / F_BLKS)   // 8
#define WROWS_PER_FCTA  (BATCH / F_BLKS)      // 1024
#define TOTAL_BLKS (BATCH + COL_BLKS)

// Scratch (device allocs forbidden). Fully rewritten every launch.
__device__ float        g_wpart[BATCH];             // w[i] * sum_j add[i][j]
__device__ float        g_bpart[COL_BLKS * NBINS];  // per-strip column sums
__device__ float        g_cpart[F_BLKS * NBINS];    // per-final-CTA partial col sums
__device__ double       g_wsum2[F_BLKS];            // per-final-CTA partial weighted sums
__device__ unsigned int g_count = 0;                // 8-way ticket; reset by last CTA

// ---------------------------------------------------------------------------
// Kernel A: fused grid. bid<64: column-sum strip. bid>=64: pair row i.
// No cross-CTA sync — the launch boundary orders everything. (Proven ~39.7us.)
// ---------------------------------------------------------------------------
__global__ __launch_bounds__(THREADS) void main_kernel(
    const float* __restrict__ outputs,
    const float* __restrict__ y,
    const float* __restrict__ weights,
    float* __restrict__ out_boost)   // -> d_out + 3
{
    __shared__ float s_add[KNN];

    cudaTriggerProgrammaticLaunchCompletion();

    const int bid = blockIdx.x;
    const int tid = threadIdx.x;

    if (bid < COL_BLKS) {
        // Column-sum strip: thread t owns bin t over 128 rows (coalesced).
        const float* p = outputs + (size_t)bid * CS_ROWS * NBINS + tid;
        float s = 0.f;
#pragma unroll
        for (int rb = 0; rb < CS_ROWS; rb += 8) {
            float t8[8];
#pragma unroll
            for (int r = 0; r < 8; r++) t8[r] = p[(size_t)(rb + r) * NBINS];
#pragma unroll
            for (int r = 0; r < 8; r++) s += t8[r];
        }
        g_bpart[bid * NBINS + tid] = s;
        return;
    }

    // Pair work for batch row i: 16 warps, warp j owns neighbor j.
    const int i    = bid - COL_BLKS;
    const int warp = tid >> 5;
    const int lane = tid & 31;

    const int nn = (int)y[i * KNN + warp];
    const float4* nbr4  = reinterpret_cast<const float4*>(outputs + (size_t)nn * NBINS);
    const float4* base4 = reinterpret_cast<const float4*>(outputs + (size_t)i  * NBINS);

    float4 n0 = nbr4[lane];
    float4 n1 = nbr4[32 + lane];
    float4 n2 = nbr4[64 + lane];
    float4 n3 = nbr4[96 + lane];
    float4 b0 = base4[lane];
    float4 b1 = base4[32 + lane];
    float4 b2 = base4[64 + lane];
    float4 b3 = base4[96 + lane];

    float m0 = fmaxf(fmaxf(b0.x + n0.x, b0.y + n0.y), fmaxf(b0.z + n0.z, b0.w + n0.w));
    float m1 = fmaxf(fmaxf(b1.x + n1.x, b1.y + n1.y), fmaxf(b1.z + n1.z, b1.w + n1.w));
    float m2 = fmaxf(fmaxf(b2.x + n2.x, b2.y + n2.y), fmaxf(b2.z + n2.z, b2.w + n2.w));
    float m3 = fmaxf(fmaxf(b3.x + n3.x, b3.y + n3.y), fmaxf(b3.z + n3.z, b3.w + n3.w));
    float m  = fmaxf(fmaxf(m0, m1), fmaxf(m2, m3));

#pragma unroll
    for (int o = 16; o; o >>= 1)
        m = fmaxf(m, __shfl_xor_sync(0xffffffffu, m, o));
    if (lane == 0) s_add[warp] = m;
    __syncthreads();

    if (tid == 0) {
        float s = 0.f;
#pragma unroll
        for (int j = 0; j < KNN; j++) s += s_add[j];
        out_boost[i] = fmaxf((2.0f - s * (1.0f / KNN)) * 0.5f, 0.5f);  // booster
        g_wpart[i]   = s * weights[i];
    }
}

// ---------------------------------------------------------------------------
// Kernel B: 8-CTA finalizer (spreads the scratch reads over 8 SMs to beat the
// single-SM MLP ceiling that made the 1-CTA version 10.8us).
//   Each CTA: partial col sums over 8 strips + partial weighted sum over 1024
//   g_wpart entries. 8-way release ticket; last CTA reduces 8 partials.
// ---------------------------------------------------------------------------
__global__ __launch_bounds__(THREADS) void final_kernel(float* __restrict__ d_out)
{
    cudaGridDependencySynchronize();   // wait for main_kernel completion

    __shared__ unsigned s_ticket;
    __shared__ double   s_ws[16];
    __shared__ float    s_mx[16];
    __shared__ float    s_mn[16];

    const int c    = blockIdx.x;
    const int tid  = threadIdx.x;
    const int warp = tid >> 5;
    const int lane = tid & 31;

    // ---- Partial column sums: thread t owns bin t over this CTA's 8 strips.
    {
        float s = 0.f;
        float t8[STRIPS_PER_FCTA];
#pragma unroll
        for (int k = 0; k < STRIPS_PER_FCTA; k++)
            t8[k] = g_bpart[(c * STRIPS_PER_FCTA + k) * NBINS + tid];
#pragma unroll
        for (int k = 0; k < STRIPS_PER_FCTA; k++) s += t8[k];
        g_cpart[c * NBINS + tid] = s;
    }

    // ---- Partial weighted sum over g_wpart[c*1024 .. c*1024+1023].
    {
        const float* w = g_wpart + c * WROWS_PER_FCTA;
        double a0 = (double)w[tid];
        double a1 = (double)w[tid + THREADS];
        double ws = a0 + a1;
#pragma unroll
        for (int o = 16; o; o >>= 1)
            ws += __shfl_xor_sync(0xffffffffu, ws, o);
        if (lane == 0) s_ws[warp] = ws;
        __syncthreads();
        if (tid == 0) {
            double t = 0.0;
#pragma unroll
            for (int wv = 0; wv < 16; wv++) t += s_ws[wv];
            g_wsum2[c] = t;
        }
    }

    // ---- 8-way release ticket.
    if (tid == 0) {
        unsigned t;
        asm volatile("atom.add.release.gpu.global.u32 %0, [%1], 1;"
                     : "=r"(t) : "l"(&g_count) : "memory");
        s_ticket = t;
    }
    __syncthreads();
    if (s_ticket != F_BLKS - 1) return;

    asm volatile("fence.acq_rel.gpu;" ::: "memory");   // acquire partials

    // ---- Last CTA: total columns (16KB, L2-hot) -> max/min; sum 8 doubles.
    float col = 0.f;
    {
        float t8[F_BLKS];
#pragma unroll
        for (int b = 0; b < F_BLKS; b++) t8[b] = __ldcg(&g_cpart[b * NBINS + tid]);
#pragma unroll
        for (int b = 0; b < F_BLKS; b++) col += t8[b];
    }
    float mx = col, mn = col;
#pragma unroll
    for (int o = 16; o; o >>= 1) {
        mx = fmaxf(mx, __shfl_xor_sync(0xffffffffu, mx, o));
        mn = fminf(mn, __shfl_xor_sync(0xffffffffu, mn, o));
    }
    if (lane == 0) { s_mx[warp] = mx; s_mn[warp] = mn; }
    __syncthreads();

    if (warp == 0) {
        float fx = (lane < 16) ? s_mx[lane] : -1e30f;
        float fn = (lane < 16) ? s_mn[lane] :  1e30f;
#pragma unroll
        for (int o = 8; o; o >>= 1) {
            fx = fmaxf(fx, __shfl_xor_sync(0xffffffffu, fx, o));
            fn = fminf(fn, __shfl_xor_sync(0xffffffffu, fn, o));
        }
        if (lane == 0) {
            double ws = 0.0;
#pragma unroll
            for (int b = 0; b < F_BLKS; b++) ws += g_wsum2[b];

            float bspread  = fx - fn;
            float ratio    = bspread / ((float)N_ROWS / (float)NBINS);
            float add_mean = (float)(ws / (double)(BATCH * KNN));
            float d        = 2.0f - add_mean;
            d = d * d;
            d_out[0] = ratio + d;   // cost
            d_out[1] = d;           // diff
            d_out[2] = ratio;       // b / target_b
            g_count  = 0;           // reset for next graph replay
        }
    }
}

// ---------------------------------------------------------------------------
extern "C" void kernel_launch(void* const* d_in, const int* in_sizes, int n_in,
                              void* d_out, int out_size)
{
    const float* outputs = (const float*)d_in[0];  // (100000, 512) f32
    const float* y       = (const float*)d_in[1];  // (8192, 16)   f32 indices
    const float* weights = (const float*)d_in[2];  // (8192,)      f32
    float* out = (float*)d_out;                    // [cost, diff, ratio, boost(8192)]

    main_kernel<<<TOTAL_BLKS, THREADS>>>(outputs, y, weights, out + 3);

    cudaLaunchConfig_t cfg = {};
    cfg.gridDim  = dim3(F_BLKS, 1, 1);
    cfg.blockDim = dim3(THREADS, 1, 1);
    cudaLaunchAttribute attr[1];
    attr[0].id = cudaLaunchAttributeProgrammaticStreamSerialization;
    attr[0].val.programmaticStreamSerializationAllowed = 1;
    cfg.attrs    = attr;
    cfg.numAttrs = 1;
    cudaLaunchKernelEx(&cfg, final_kernel, out);
}